// round 3
// baseline (speedup 1.0000x reference)
#include <cuda_runtime.h>
#include <cstdint>

#define HIDDEN   2048
#define SEQ      4096
#define NTOK     16384          // B*S = 4*4096
#define MODULUS  65535LL
#define GATE_BIAS (-4.0f)

// -------- static scratch (no dynamic allocation allowed) --------
__device__ float g_memory[(size_t)NTOK * HIDDEN];   // gathered table rows
__device__ float g_key   [(size_t)NTOK * HIDDEN];   // Wk out (pre-norm), then gated
__device__ float g_val   [(size_t)NTOK * HIDDEN];   // Wv out (pre-norm)

// normalized hash params (always int64 semantics of the reference)
__device__ long long n_hm2[8];
__device__ long long n_ho2[4];
__device__ long long n_hm3[12];
__device__ long long n_ho3[4];
__device__ int       g_ids_is32;

// ============================================================================
// Kernel 0: detect on-device storage width of the integer inputs and
// normalize hash params to int64.
//  - If params are stored int64: int32 words at odd positions are the high
//    halves of values < 2^32  -> exactly 0. Multipliers are never 0.
//  - If stored int32: odd positions hold real (nonzero) multiplier words.
//  - ids: values in [0,10240); if stored int64, odd int32 words are all 0.
//    32 probes of random ids being all 0 under int32 storage: ~impossible.
// All probes read <= n int32 words, safe under either interpretation.
// ============================================================================
__global__ void k_norm(const int* __restrict__ hm2, const int* __restrict__ ho2,
                       const int* __restrict__ hm3, const int* __restrict__ ho3,
                       const int* __restrict__ ids)
{
    const bool p64 = (hm2[1] == 0) && (hm2[3] == 0) && (hm2[5] == 0) && (hm2[7] == 0);
    if (p64) {
        const long long* h2 = (const long long*)hm2;
        const long long* o2 = (const long long*)ho2;
        const long long* h3 = (const long long*)hm3;
        const long long* o3 = (const long long*)ho3;
        for (int i = 0; i < 8;  i++) n_hm2[i] = h2[i];
        for (int i = 0; i < 4;  i++) n_ho2[i] = o2[i];
        for (int i = 0; i < 12; i++) n_hm3[i] = h3[i];
        for (int i = 0; i < 4;  i++) n_ho3[i] = o3[i];
    } else {
        // int32 storage: values were wrapped mod 2^32; originals < 2^32,
        // so a uint32 reinterpret recovers them exactly.
        for (int i = 0; i < 8;  i++) n_hm2[i] = (long long)(unsigned int)hm2[i];
        for (int i = 0; i < 4;  i++) n_ho2[i] = (long long)(unsigned int)ho2[i];
        for (int i = 0; i < 12; i++) n_hm3[i] = (long long)(unsigned int)hm3[i];
        for (int i = 0; i < 4;  i++) n_ho3[i] = (long long)(unsigned int)ho3[i];
    }
    bool i64 = true;
    for (int i = 1; i < 64; i += 2) {
        if (ids[i] != 0) { i64 = false; break; }
    }
    g_ids_is32 = i64 ? 0 : 1;
}

// ============================================================================
// Kernel 1: n-gram hashing + table gather.
// One block per token, 256 threads. Threads 0..7 compute the 8 hash ids
// (4 heads of bigram, 4 heads of trigram), then all 256 threads gather the
// 8 x 256-float rows (fully coalesced 1KB row reads).
// ============================================================================
__global__ void k_hash_gather(const void* __restrict__ ids_raw,
                              const float* __restrict__ tables)
{
    const int tok = blockIdx.x;
    const int tid = threadIdx.x;
    const int b = tok >> 12;
    const int s = tok & (SEQ - 1);

    __shared__ int sh_id[8];
    if (tid < 8) {
        const int head = tid & 3;
        const int ng   = tid >> 2;      // 0 -> n=2, 1 -> n=3
        const int is32 = g_ids_is32;
        const long long* row64 = (const long long*)ids_raw + (size_t)b * SEQ;
        const int*       row32 = (const int*)      ids_raw + (size_t)b * SEQ;
        #define IDAT(x) (is32 ? (long long)row32[(x)] : row64[(x)])
        long long idv = 0;
        if (ng == 0) {
            if (s >= 1) {
                long long mix = (IDAT(s - 1) * n_hm2[head * 2 + 0])
                              ^ (IDAT(s)     * n_hm2[head * 2 + 1]);
                idv = (mix + n_ho2[head]) % MODULUS + 1;
            }
        } else {
            if (s >= 2) {
                long long mix = (IDAT(s - 2) * n_hm3[head * 3 + 0])
                              ^ (IDAT(s - 1) * n_hm3[head * 3 + 1])
                              ^ (IDAT(s)     * n_hm3[head * 3 + 2]);
                idv = (mix + n_ho3[head]) % MODULUS + 1;
            }
        }
        #undef IDAT
        // defensive clamp: never allow an OOB gather
        if (idv < 0) idv = 0;
        if (idv > 65535) idv = 65535;
        sh_id[tid] = (int)idv;
    }
    __syncthreads();

    float* dst = g_memory + (size_t)tok * HIDDEN;
#pragma unroll
    for (int h = 0; h < 8; h++) {
        size_t src = ((size_t)h * 65536 + (size_t)sh_id[h]) * 256 + tid;
        dst[h * 256 + tid] = __ldg(tables + src);
    }
}

// ============================================================================
// Kernel 2: fused dual GEMM  C = memory @ W^T  for W in {Wk, Wv}.
// tf32 mma.sync m16n8k8, BM=128 BN=128 BK=32, 256 threads (8 warps),
// warp tile 64x32 (4 m-tiles x 4 n-tiles).
// blockIdx.y in [0,32): first 16 n-tiles -> Wk/g_key, last 16 -> Wv/g_val.
// ============================================================================
#define BM 128
#define BN 128
#define BK 32
#define SSTR 36   // padded stride -> conflict-free fragment loads

__device__ __forceinline__ uint32_t f2tf32(float x) {
    uint32_t r;
    asm("cvt.rna.tf32.f32 %0, %1;" : "=r"(r) : "f"(x));
    return r;
}

__global__ __launch_bounds__(256) void k_gemm(const float* __restrict__ Wk,
                                              const float* __restrict__ Wv)
{
    __shared__ uint32_t As[BM * SSTR];
    __shared__ uint32_t Bs[BN * SSTR];

    const int bm  = blockIdx.x;
    const int bn  = blockIdx.y;
    const int tid = threadIdx.x;

    const float* A  = g_memory + (size_t)bm * BM * HIDDEN;
    const float* W  = (bn < 16) ? Wk : Wv;
    const int nloc  = (bn & 15) * BN;
    const float* Bg = W + (size_t)nloc * HIDDEN;
    float* Cg = ((bn < 16) ? g_key : g_val) + (size_t)bm * BM * HIDDEN + nloc;

    const int warp = tid >> 5;
    const int lane = tid & 31;
    const int wm = (warp & 1) * 64;    // warp M offset: 0 or 64
    const int wn = (warp >> 1) * 32;   // warp N offset: 0,32,64,96
    const int g  = lane >> 2;          // group id (0..7)
    const int c  = lane & 3;           // thread-in-group (0..3)

    float acc[4][4][4];
#pragma unroll
    for (int mt = 0; mt < 4; mt++)
#pragma unroll
        for (int nt = 0; nt < 4; nt++)
#pragma unroll
            for (int i = 0; i < 4; i++) acc[mt][nt][i] = 0.f;

    for (int kk = 0; kk < HIDDEN; kk += BK) {
        // ---- global -> shared (tf32-rounded), 128x32 each ----
#pragma unroll
        for (int i = 0; i < 4; i++) {
            int slot = tid + i * 256;          // 1024 float4 slots
            int r    = slot >> 3;
            int c4   = (slot & 7) * 4;
            float4 va = *(const float4*)(A  + (size_t)r * HIDDEN + kk + c4);
            float4 vb = *(const float4*)(Bg + (size_t)r * HIDDEN + kk + c4);
            As[r * SSTR + c4 + 0] = f2tf32(va.x);
            As[r * SSTR + c4 + 1] = f2tf32(va.y);
            As[r * SSTR + c4 + 2] = f2tf32(va.z);
            As[r * SSTR + c4 + 3] = f2tf32(va.w);
            Bs[r * SSTR + c4 + 0] = f2tf32(vb.x);
            Bs[r * SSTR + c4 + 1] = f2tf32(vb.y);
            Bs[r * SSTR + c4 + 2] = f2tf32(vb.z);
            Bs[r * SSTR + c4 + 3] = f2tf32(vb.w);
        }
        __syncthreads();

        // ---- 4 k-steps of 8 ----
#pragma unroll
        for (int ks = 0; ks < 4; ks++) {
            const int k0 = ks * 8;
            uint32_t a[4][4];
            uint32_t bf[4][2];
#pragma unroll
            for (int mt = 0; mt < 4; mt++) {
                int r = wm + mt * 16;
                a[mt][0] = As[(r + g)     * SSTR + k0 + c];
                a[mt][1] = As[(r + g + 8) * SSTR + k0 + c];
                a[mt][2] = As[(r + g)     * SSTR + k0 + c + 4];
                a[mt][3] = As[(r + g + 8) * SSTR + k0 + c + 4];
            }
#pragma unroll
            for (int nt = 0; nt < 4; nt++) {
                int col = wn + nt * 8;
                bf[nt][0] = Bs[(col + g) * SSTR + k0 + c];
                bf[nt][1] = Bs[(col + g) * SSTR + k0 + c + 4];
            }
#pragma unroll
            for (int mt = 0; mt < 4; mt++)
#pragma unroll
                for (int nt = 0; nt < 4; nt++) {
                    asm volatile(
                        "mma.sync.aligned.m16n8k8.row.col.f32.tf32.tf32.f32 "
                        "{%0,%1,%2,%3},{%4,%5,%6,%7},{%8,%9},{%0,%1,%2,%3};"
                        : "+f"(acc[mt][nt][0]), "+f"(acc[mt][nt][1]),
                          "+f"(acc[mt][nt][2]), "+f"(acc[mt][nt][3])
                        : "r"(a[mt][0]), "r"(a[mt][1]), "r"(a[mt][2]), "r"(a[mt][3]),
                          "r"(bf[nt][0]), "r"(bf[nt][1]));
                }
        }
        __syncthreads();
    }

    // ---- epilogue ----
#pragma unroll
    for (int mt = 0; mt < 4; mt++) {
#pragma unroll
        for (int nt = 0; nt < 4; nt++) {
            int r0 = wm + mt * 16 + g;
            int cc = wn + nt * 8 + c * 2;
            *(float2*)(Cg + (size_t)r0 * HIDDEN + cc) =
                make_float2(acc[mt][nt][0], acc[mt][nt][1]);
            *(float2*)(Cg + (size_t)(r0 + 8) * HIDDEN + cc) =
                make_float2(acc[mt][nt][2], acc[mt][nt][3]);
        }
    }
}

// ============================================================================
// Kernel 3: per-token rmsnorm(key), rmsnorm(value), gate, gated value.
// One block (256 threads) per token; 8 elements per thread.
// Writes the gated result IN PLACE into g_key (key no longer needed).
// ============================================================================
__global__ void k_gate(const float* __restrict__ hidden,
                       const float* __restrict__ kw,
                       const float* __restrict__ vw)
{
    const int tok = blockIdx.x;
    const int tid = threadIdx.x;
    const float* key = g_key + (size_t)tok * HIDDEN;
    const float* val = g_val + (size_t)tok * HIDDEN;
    const float* hh  = hidden + (size_t)tok * HIDDEN;

    float vv[8], wvv[8];
    float s1 = 0.f, s2 = 0.f, s3 = 0.f;
#pragma unroll
    for (int i = 0; i < 8; i++) {
        int d = tid + i * 256;
        float k = key[d];
        float v = val[d];
        float h = hh[d];
        float wk = kw[d];
        wvv[i] = vw[d];
        vv[i]  = v;
        s1 += k * k;
        s2 += v * v;
        s3 += h * wk * k;
    }
#pragma unroll
    for (int o = 16; o; o >>= 1) {
        s1 += __shfl_xor_sync(0xffffffffu, s1, o);
        s2 += __shfl_xor_sync(0xffffffffu, s2, o);
        s3 += __shfl_xor_sync(0xffffffffu, s3, o);
    }
    __shared__ float red[3][8];
    if ((tid & 31) == 0) {
        red[0][tid >> 5] = s1;
        red[1][tid >> 5] = s2;
        red[2][tid >> 5] = s3;
    }
    __syncthreads();
    float S1 = 0.f, S2 = 0.f, S3 = 0.f;
#pragma unroll
    for (int w = 0; w < 8; w++) { S1 += red[0][w]; S2 += red[1][w]; S3 += red[2][w]; }

    const float rk = rsqrtf(S1 * (1.0f / HIDDEN) + 1e-6f);
    const float rv = rsqrtf(S2 * (1.0f / HIDDEN) + 1e-6f);
    const float logit = S3 * rk * (1.0f / 45.254833995939045f) + GATE_BIAS;
    const float gate  = 1.0f / (1.0f + expf(-logit));

    float* out = g_key + (size_t)tok * HIDDEN;   // reuse key buffer for gated
#pragma unroll
    for (int i = 0; i < 8; i++) {
        int d = tid + i * 256;
        out[d] = gate * wvv[i] * vv[i] * rv;
    }
}

// ============================================================================
// Kernel 4: causal depthwise conv (K=3) + residual, reading gated from g_key.
// out[s] = gated[s] + w0*gated[s-2] + w1*gated[s-1] + w2*gated[s]
// ============================================================================
__global__ void k_conv(const float* __restrict__ conv_w,
                       float* __restrict__ out)
{
    const int tok = blockIdx.y;
    const int d   = blockIdx.x * 256 + threadIdx.x;
    const int s   = tok & (SEQ - 1);
    const size_t base = (size_t)tok * HIDDEN + d;

    float g2 = g_key[base];
    float g1 = (s >= 1) ? g_key[base - HIDDEN]     : 0.f;
    float g0 = (s >= 2) ? g_key[base - 2 * HIDDEN] : 0.f;
    float w0 = conv_w[d * 3 + 0];
    float w1 = conv_w[d * 3 + 1];
    float w2 = conv_w[d * 3 + 2];
    out[base] = g2 + w0 * g0 + w1 * g1 + w2 * g2;
}

// ============================================================================
// Input identification by element count (robust to metadata ordering as long
// as same-size pairs keep dict/alphabetical relative order, which both do):
//   33554432 -> hidden_states      16384 -> input_ids
//  134217728 -> tables           4194304 -> Wk (1st), Wv (2nd)
//       2048 -> key_norm_w (1st), value_norm_w (2nd)
//       6144 -> conv_w                 8 -> hm2
//         12 -> hm3                    4 -> ho2 (1st), ho3 (2nd)
// ============================================================================
extern "C" void kernel_launch(void* const* d_in, const int* in_sizes, int n_in,
                              void* d_out, int out_size)
{
    const float* hidden = nullptr;
    const void*  ids    = nullptr;
    const float* tables = nullptr;
    const float* Wk = nullptr, *Wv = nullptr;
    const float* knw = nullptr, *vnw = nullptr;
    const float* convw = nullptr;
    const int*   hm2 = nullptr, *ho2 = nullptr, *hm3 = nullptr, *ho3 = nullptr;

    for (int i = 0; i < n_in; i++) {
        const int sz = in_sizes[i];
        void* p = d_in[i];
        switch (sz) {
            case 33554432:  hidden = (const float*)p; break;
            case 16384:     ids    = (const void*)p; break;
            case 134217728: tables = (const float*)p; break;
            case 4194304:   if (!Wk) Wk = (const float*)p; else Wv = (const float*)p; break;
            case 2048:      if (!knw) knw = (const float*)p; else vnw = (const float*)p; break;
            case 6144:      convw = (const float*)p; break;
            case 8:         hm2 = (const int*)p; break;
            case 12:        hm3 = (const int*)p; break;
            case 4:         if (!ho2) ho2 = (const int*)p; else ho3 = (const int*)p; break;
            default: break;
        }
    }
    float* out = (float*)d_out;

    k_norm<<<1, 1>>>(hm2, ho2, hm3, ho3, (const int*)ids);
    k_hash_gather<<<NTOK, 256>>>(ids, tables);
    k_gemm<<<dim3(NTOK / BM, 32), 256>>>(Wk, Wv);
    k_gate<<<NTOK, 256>>>(hidden, knw, vnw);
    k_conv<<<dim3(HIDDEN / 256, NTOK), 256>>>(convw, out);
}

// round 4
// speedup vs baseline: 1.1714x; 1.1714x over previous
#include <cuda_runtime.h>
#include <cstdint>

#define HIDDEN   2048
#define SEQ      4096
#define NTOK     16384          // B*S = 4*4096
#define MODULUS  65535LL
#define GATE_BIAS (-4.0f)

// -------- static scratch (no dynamic allocation allowed) --------
__device__ float g_memory[(size_t)NTOK * HIDDEN];   // gathered rows (tf32-rounded)
__device__ float g_key   [(size_t)NTOK * HIDDEN];   // Wk out (pre-norm), then gated
__device__ float g_val   [(size_t)NTOK * HIDDEN];   // Wv out (pre-norm)
__device__ float g_w     [(size_t)2 * HIDDEN * HIDDEN]; // tf32-rounded Wk|Wv

// normalized hash params (always int64 semantics of the reference)
__device__ long long n_hm2[8];
__device__ long long n_ho2[4];
__device__ long long n_hm3[12];
__device__ long long n_ho3[4];
__device__ int       g_ids_is32;

__device__ __forceinline__ uint32_t f2tf32(float x) {
    uint32_t r;
    asm("cvt.rna.tf32.f32 %0, %1;" : "=r"(r) : "f"(x));
    return r;
}

// ============================================================================
// Kernel 0: detect storage width of integer inputs, normalize params to i64.
// ============================================================================
__global__ void k_norm(const int* __restrict__ hm2, const int* __restrict__ ho2,
                       const int* __restrict__ hm3, const int* __restrict__ ho3,
                       const int* __restrict__ ids)
{
    const bool p64 = (hm2[1] == 0) && (hm2[3] == 0) && (hm2[5] == 0) && (hm2[7] == 0);
    if (p64) {
        const long long* h2 = (const long long*)hm2;
        const long long* o2 = (const long long*)ho2;
        const long long* h3 = (const long long*)hm3;
        const long long* o3 = (const long long*)ho3;
        for (int i = 0; i < 8;  i++) n_hm2[i] = h2[i];
        for (int i = 0; i < 4;  i++) n_ho2[i] = o2[i];
        for (int i = 0; i < 12; i++) n_hm3[i] = h3[i];
        for (int i = 0; i < 4;  i++) n_ho3[i] = o3[i];
    } else {
        for (int i = 0; i < 8;  i++) n_hm2[i] = (long long)(unsigned int)hm2[i];
        for (int i = 0; i < 4;  i++) n_ho2[i] = (long long)(unsigned int)ho2[i];
        for (int i = 0; i < 12; i++) n_hm3[i] = (long long)(unsigned int)hm3[i];
        for (int i = 0; i < 4;  i++) n_ho3[i] = (long long)(unsigned int)ho3[i];
    }
    bool i64 = true;
    for (int i = 1; i < 64; i += 2) {
        if (ids[i] != 0) { i64 = false; break; }
    }
    g_ids_is32 = i64 ? 0 : 1;
}

// ============================================================================
// Kernel 0b: tf32-round Wk|Wv into g_w (done once per launch; ~10us)
// ============================================================================
__global__ void k_roundW(const float* __restrict__ Wk, const float* __restrict__ Wv)
{
    size_t i = (size_t)blockIdx.x * 256 + threadIdx.x;
    g_w[i]                               = __uint_as_float(f2tf32(Wk[i]));
    g_w[(size_t)HIDDEN * HIDDEN + i]     = __uint_as_float(f2tf32(Wv[i]));
}

// ============================================================================
// Kernel 1: n-gram hashing + table gather (writes tf32-rounded rows).
// ============================================================================
__global__ void k_hash_gather(const void* __restrict__ ids_raw,
                              const float* __restrict__ tables)
{
    const int tok = blockIdx.x;
    const int tid = threadIdx.x;
    const int b = tok >> 12;
    const int s = tok & (SEQ - 1);

    __shared__ int sh_id[8];
    if (tid < 8) {
        const int head = tid & 3;
        const int ng   = tid >> 2;
        const int is32 = g_ids_is32;
        const long long* row64 = (const long long*)ids_raw + (size_t)b * SEQ;
        const int*       row32 = (const int*)      ids_raw + (size_t)b * SEQ;
        #define IDAT(x) (is32 ? (long long)row32[(x)] : row64[(x)])
        long long idv = 0;
        if (ng == 0) {
            if (s >= 1) {
                long long mix = (IDAT(s - 1) * n_hm2[head * 2 + 0])
                              ^ (IDAT(s)     * n_hm2[head * 2 + 1]);
                idv = (mix + n_ho2[head]) % MODULUS + 1;
            }
        } else {
            if (s >= 2) {
                long long mix = (IDAT(s - 2) * n_hm3[head * 3 + 0])
                              ^ (IDAT(s - 1) * n_hm3[head * 3 + 1])
                              ^ (IDAT(s)     * n_hm3[head * 3 + 2]);
                idv = (mix + n_ho3[head]) % MODULUS + 1;
            }
        }
        #undef IDAT
        if (idv < 0) idv = 0;
        if (idv > 65535) idv = 65535;
        sh_id[tid] = (int)idv;
    }
    __syncthreads();

    float* dst = g_memory + (size_t)tok * HIDDEN;
#pragma unroll
    for (int h = 0; h < 8; h++) {
        size_t src = ((size_t)h * 65536 + (size_t)sh_id[h]) * 256 + tid;
        dst[h * 256 + tid] = __uint_as_float(f2tf32(__ldg(tables + src)));
    }
}

// ============================================================================
// Kernel 2: fused dual GEMM  C = memory @ W^T, W in {Wk, Wv} (pre-rounded).
// tf32 mma.sync m16n8k8. BM=128 BN=128 BK=16, 3-stage cp.async pipeline,
// XOR-swizzled smem (conflict-free, no padding, 48KB static).
// grid = (32, 128): x = n-block (16 Wk + 16 Wv), y = m-block -> blocks that
// share an A tile are consecutive -> A read from L2, not DRAM.
// ============================================================================
#define BM 128
#define BN 128
#define BK 16
#define NSTAGE 3

__device__ __forceinline__ void cp16(uint32_t* smem_dst, const float* gsrc) {
    uint32_t d = (uint32_t)__cvta_generic_to_shared(smem_dst);
    asm volatile("cp.async.cg.shared.global [%0], [%1], 16;" :: "r"(d), "l"(gsrc));
}

// element (r, k) of a BMxBK tile lives at  r*16 + ((k>>2) ^ ((r>>1)&3))*4 + (k&3)
__device__ __forceinline__ int swidx(int r, int kq, int c) {
    return r * BK + (((kq) ^ ((r >> 1) & 3)) << 2) + c;
}

__global__ __launch_bounds__(256) void k_gemm()
{
    __shared__ uint32_t As[NSTAGE][BM * BK];
    __shared__ uint32_t Bs[NSTAGE][BN * BK];

    const int bn  = blockIdx.x;          // 0..31 (fast)
    const int bm  = blockIdx.y;          // 0..127
    const int tid = threadIdx.x;

    const float* A  = g_memory + (size_t)bm * BM * HIDDEN;
    const int sel   = bn >> 4;           // 0 = Wk, 1 = Wv
    const int nloc  = (bn & 15) * BN;
    const float* Bg = g_w + (size_t)sel * HIDDEN * HIDDEN + (size_t)nloc * HIDDEN;
    float* Cg = (sel ? g_val : g_key) + (size_t)bm * BM * HIDDEN + nloc;

    const int warp = tid >> 5;
    const int lane = tid & 31;
    const int wm = (warp & 1) * 64;
    const int wn = (warp >> 1) * 32;
    const int g  = lane >> 2;
    const int c  = lane & 3;

    // per-thread copy slots: 2 chunks of A + 2 of B per stage
    const int r0  = tid >> 2;            // chunk 0 row (0..63)
    const int cc0 = tid & 3;
    const int r1  = r0 + 64;             // chunk 1 row (64..127)
    const int sw0 = swidx(r0, cc0, 0);
    const int sw1 = swidx(r1, cc0, 0);

    float acc[4][4][4];
#pragma unroll
    for (int mt = 0; mt < 4; mt++)
#pragma unroll
        for (int nt = 0; nt < 4; nt++)
#pragma unroll
            for (int i = 0; i < 4; i++) acc[mt][nt][i] = 0.f;

    const int NST = HIDDEN / BK;         // 128 stages

    // ---- prologue: issue stages 0 and 1 ----
#pragma unroll
    for (int st = 0; st < 2; st++) {
        const int kk = st * BK;
        cp16(&As[st][sw0], A  + (size_t)r0 * HIDDEN + kk + cc0 * 4);
        cp16(&As[st][sw1], A  + (size_t)r1 * HIDDEN + kk + cc0 * 4);
        cp16(&Bs[st][sw0], Bg + (size_t)r0 * HIDDEN + kk + cc0 * 4);
        cp16(&Bs[st][sw1], Bg + (size_t)r1 * HIDDEN + kk + cc0 * 4);
        asm volatile("cp.async.commit_group;" ::: "memory");
    }

    for (int i = 0; i < NST; i++) {
        asm volatile("cp.async.wait_group 1;" ::: "memory");
        __syncthreads();

        const int nxt = i + 2;
        if (nxt < NST) {
            const int buf = nxt % NSTAGE;
            const int kk  = nxt * BK;
            cp16(&As[buf][sw0], A  + (size_t)r0 * HIDDEN + kk + cc0 * 4);
            cp16(&As[buf][sw1], A  + (size_t)r1 * HIDDEN + kk + cc0 * 4);
            cp16(&Bs[buf][sw0], Bg + (size_t)r0 * HIDDEN + kk + cc0 * 4);
            cp16(&Bs[buf][sw1], Bg + (size_t)r1 * HIDDEN + kk + cc0 * 4);
        }
        asm volatile("cp.async.commit_group;" ::: "memory");

        const uint32_t* as = As[i % NSTAGE];
        const uint32_t* bs = Bs[i % NSTAGE];

#pragma unroll
        for (int ks = 0; ks < 2; ks++) {
            const int q0 = ks * 2;       // k>>2 base: 0 or 2
            uint32_t a[4][4];
            uint32_t bf[4][2];
#pragma unroll
            for (int mt = 0; mt < 4; mt++) {
                int ra = wm + mt * 16 + g;
                a[mt][0] = as[swidx(ra,     q0,     c)];
                a[mt][1] = as[swidx(ra + 8, q0,     c)];
                a[mt][2] = as[swidx(ra,     q0 + 1, c)];
                a[mt][3] = as[swidx(ra + 8, q0 + 1, c)];
            }
#pragma unroll
            for (int nt = 0; nt < 4; nt++) {
                int rb = wn + nt * 8 + g;
                bf[nt][0] = bs[swidx(rb, q0,     c)];
                bf[nt][1] = bs[swidx(rb, q0 + 1, c)];
            }
#pragma unroll
            for (int mt = 0; mt < 4; mt++)
#pragma unroll
                for (int nt = 0; nt < 4; nt++) {
                    asm volatile(
                        "mma.sync.aligned.m16n8k8.row.col.f32.tf32.tf32.f32 "
                        "{%0,%1,%2,%3},{%4,%5,%6,%7},{%8,%9},{%0,%1,%2,%3};"
                        : "+f"(acc[mt][nt][0]), "+f"(acc[mt][nt][1]),
                          "+f"(acc[mt][nt][2]), "+f"(acc[mt][nt][3])
                        : "r"(a[mt][0]), "r"(a[mt][1]), "r"(a[mt][2]), "r"(a[mt][3]),
                          "r"(bf[nt][0]), "r"(bf[nt][1]));
                }
        }
    }

    // ---- epilogue ----
#pragma unroll
    for (int mt = 0; mt < 4; mt++) {
#pragma unroll
        for (int nt = 0; nt < 4; nt++) {
            int rr = wm + mt * 16 + g;
            int cc = wn + nt * 8 + c * 2;
            *(float2*)(Cg + (size_t)rr * HIDDEN + cc) =
                make_float2(acc[mt][nt][0], acc[mt][nt][1]);
            *(float2*)(Cg + (size_t)(rr + 8) * HIDDEN + cc) =
                make_float2(acc[mt][nt][2], acc[mt][nt][3]);
        }
    }
}

// ============================================================================
// Kernel 3: per-token rmsnorm(key), rmsnorm(value), gate, gated value.
// Writes gated IN PLACE into g_key.
// ============================================================================
__global__ void k_gate(const float* __restrict__ hidden,
                       const float* __restrict__ kw,
                       const float* __restrict__ vw)
{
    const int tok = blockIdx.x;
    const int tid = threadIdx.x;
    const float* key = g_key + (size_t)tok * HIDDEN;
    const float* val = g_val + (size_t)tok * HIDDEN;
    const float* hh  = hidden + (size_t)tok * HIDDEN;

    float vv[8], wvv[8];
    float s1 = 0.f, s2 = 0.f, s3 = 0.f;
#pragma unroll
    for (int i = 0; i < 8; i++) {
        int d = tid + i * 256;
        float k = key[d];
        float v = val[d];
        float h = hh[d];
        float wk = kw[d];
        wvv[i] = vw[d];
        vv[i]  = v;
        s1 += k * k;
        s2 += v * v;
        s3 += h * wk * k;
    }
#pragma unroll
    for (int o = 16; o; o >>= 1) {
        s1 += __shfl_xor_sync(0xffffffffu, s1, o);
        s2 += __shfl_xor_sync(0xffffffffu, s2, o);
        s3 += __shfl_xor_sync(0xffffffffu, s3, o);
    }
    __shared__ float red[3][8];
    if ((tid & 31) == 0) {
        red[0][tid >> 5] = s1;
        red[1][tid >> 5] = s2;
        red[2][tid >> 5] = s3;
    }
    __syncthreads();
    float S1 = 0.f, S2 = 0.f, S3 = 0.f;
#pragma unroll
    for (int w = 0; w < 8; w++) { S1 += red[0][w]; S2 += red[1][w]; S3 += red[2][w]; }

    const float rk = rsqrtf(S1 * (1.0f / HIDDEN) + 1e-6f);
    const float rv = rsqrtf(S2 * (1.0f / HIDDEN) + 1e-6f);
    const float logit = S3 * rk * (1.0f / 45.254833995939045f) + GATE_BIAS;
    const float gate  = 1.0f / (1.0f + expf(-logit));

    float* out = g_key + (size_t)tok * HIDDEN;
#pragma unroll
    for (int i = 0; i < 8; i++) {
        int d = tid + i * 256;
        out[d] = gate * wvv[i] * vv[i] * rv;
    }
}

// ============================================================================
// Kernel 4: causal depthwise conv (K=3) + residual, gated lives in g_key.
// ============================================================================
__global__ void k_conv(const float* __restrict__ conv_w,
                       float* __restrict__ out)
{
    const int tok = blockIdx.y;
    const int d   = blockIdx.x * 256 + threadIdx.x;
    const int s   = tok & (SEQ - 1);
    const size_t base = (size_t)tok * HIDDEN + d;

    float g2 = g_key[base];
    float g1 = (s >= 1) ? g_key[base - HIDDEN]     : 0.f;
    float g0 = (s >= 2) ? g_key[base - 2 * HIDDEN] : 0.f;
    float w0 = conv_w[d * 3 + 0];
    float w1 = conv_w[d * 3 + 1];
    float w2 = conv_w[d * 3 + 2];
    out[base] = g2 + w0 * g0 + w1 * g1 + w2 * g2;
}

// ============================================================================
extern "C" void kernel_launch(void* const* d_in, const int* in_sizes, int n_in,
                              void* d_out, int out_size)
{
    const float* hidden = nullptr;
    const void*  ids    = nullptr;
    const float* tables = nullptr;
    const float* Wk = nullptr, *Wv = nullptr;
    const float* knw = nullptr, *vnw = nullptr;
    const float* convw = nullptr;
    const int*   hm2 = nullptr, *ho2 = nullptr, *hm3 = nullptr, *ho3 = nullptr;

    for (int i = 0; i < n_in; i++) {
        const int sz = in_sizes[i];
        void* p = d_in[i];
        switch (sz) {
            case 33554432:  hidden = (const float*)p; break;
            case 16384:     ids    = (const void*)p; break;
            case 134217728: tables = (const float*)p; break;
            case 4194304:   if (!Wk) Wk = (const float*)p; else Wv = (const float*)p; break;
            case 2048:      if (!knw) knw = (const float*)p; else vnw = (const float*)p; break;
            case 6144:      convw = (const float*)p; break;
            case 8:         hm2 = (const int*)p; break;
            case 12:        hm3 = (const int*)p; break;
            case 4:         if (!ho2) ho2 = (const int*)p; else ho3 = (const int*)p; break;
            default: break;
        }
    }
    float* out = (float*)d_out;

    k_norm<<<1, 1>>>(hm2, ho2, hm3, ho3, (const int*)ids);
    k_roundW<<<HIDDEN * HIDDEN / 256, 256>>>(Wk, Wv);
    k_hash_gather<<<NTOK, 256>>>(ids, tables);
    k_gemm<<<dim3(32, NTOK / BM), 256>>>();
    k_gate<<<NTOK, 256>>>(hidden, knw, vnw);
    k_conv<<<dim3(HIDDEN / 256, NTOK), 256>>>(convw, out);
}

// round 6
// speedup vs baseline: 2.0281x; 1.7314x over previous
#include <cuda_runtime.h>
#include <cuda_fp16.h>
#include <cstdint>

#define HIDDEN   2048
#define SEQ      4096
#define NTOK     16384          // B*S = 4*4096
#define MODULUS  65535LL
#define GATE_BIAS (-4.0f)

// -------- static scratch (no dynamic allocation allowed) --------
__device__ __half g_mem_h[(size_t)NTOK * HIDDEN];        // gathered rows (fp16)
__device__ __half g_w_h  [(size_t)2 * HIDDEN * HIDDEN];  // fp16 Wk|Wv
__device__ float  g_key  [(size_t)NTOK * HIDDEN];        // Wk out, then gated
__device__ float  g_val  [(size_t)NTOK * HIDDEN];        // Wv out

// normalized hash params (always int64 semantics of the reference)
__device__ long long n_hm2[8];
__device__ long long n_ho2[4];
__device__ long long n_hm3[12];
__device__ long long n_ho3[4];
__device__ int       g_ids_is32;

// ============================================================================
// Kernel 0: detect storage width of integer inputs, normalize params to i64.
// ============================================================================
__global__ void k_norm(const int* __restrict__ hm2, const int* __restrict__ ho2,
                       const int* __restrict__ hm3, const int* __restrict__ ho3,
                       const int* __restrict__ ids)
{
    const bool p64 = (hm2[1] == 0) && (hm2[3] == 0) && (hm2[5] == 0) && (hm2[7] == 0);
    if (p64) {
        const long long* h2 = (const long long*)hm2;
        const long long* o2 = (const long long*)ho2;
        const long long* h3 = (const long long*)hm3;
        const long long* o3 = (const long long*)ho3;
        for (int i = 0; i < 8;  i++) n_hm2[i] = h2[i];
        for (int i = 0; i < 4;  i++) n_ho2[i] = o2[i];
        for (int i = 0; i < 12; i++) n_hm3[i] = h3[i];
        for (int i = 0; i < 4;  i++) n_ho3[i] = o3[i];
    } else {
        for (int i = 0; i < 8;  i++) n_hm2[i] = (long long)(unsigned int)hm2[i];
        for (int i = 0; i < 4;  i++) n_ho2[i] = (long long)(unsigned int)ho2[i];
        for (int i = 0; i < 12; i++) n_hm3[i] = (long long)(unsigned int)hm3[i];
        for (int i = 0; i < 4;  i++) n_ho3[i] = (long long)(unsigned int)ho3[i];
    }
    bool i64 = true;
    for (int i = 1; i < 64; i += 2) {
        if (ids[i] != 0) { i64 = false; break; }
    }
    g_ids_is32 = i64 ? 0 : 1;
}

// ============================================================================
// Kernel 0b: fp16-round Wk|Wv into g_w_h (half2 stores).
// ============================================================================
__global__ void k_roundW(const float* __restrict__ Wk, const float* __restrict__ Wv)
{
    size_t i = (size_t)blockIdx.x * 256 + threadIdx.x;   // pair index
    float2 a = *(const float2*)(Wk + 2 * i);
    float2 b = *(const float2*)(Wv + 2 * i);
    *(__half2*)(g_w_h + 2 * i) = __floats2half2_rn(a.x, a.y);
    *(__half2*)(g_w_h + (size_t)HIDDEN * HIDDEN + 2 * i) = __floats2half2_rn(b.x, b.y);
}

// ============================================================================
// Kernel 1: n-gram hashing + table gather (fp16 output, half2 stores).
// 128 threads per token; each thread handles 2 columns of each 256-wide head.
// ============================================================================
__global__ void k_hash_gather(const void* __restrict__ ids_raw,
                              const float* __restrict__ tables)
{
    const int tok = blockIdx.x;
    const int tid = threadIdx.x;          // 0..127
    const int b = tok >> 12;
    const int s = tok & (SEQ - 1);

    __shared__ int sh_id[8];
    if (tid < 8) {
        const int head = tid & 3;
        const int ng   = tid >> 2;
        const int is32 = g_ids_is32;
        const long long* row64 = (const long long*)ids_raw + (size_t)b * SEQ;
        const int*       row32 = (const int*)      ids_raw + (size_t)b * SEQ;
        #define IDAT(x) (is32 ? (long long)row32[(x)] : row64[(x)])
        long long idv = 0;
        if (ng == 0) {
            if (s >= 1) {
                long long mix = (IDAT(s - 1) * n_hm2[head * 2 + 0])
                              ^ (IDAT(s)     * n_hm2[head * 2 + 1]);
                idv = (mix + n_ho2[head]) % MODULUS + 1;
            }
        } else {
            if (s >= 2) {
                long long mix = (IDAT(s - 2) * n_hm3[head * 3 + 0])
                              ^ (IDAT(s - 1) * n_hm3[head * 3 + 1])
                              ^ (IDAT(s)     * n_hm3[head * 3 + 2]);
                idv = (mix + n_ho3[head]) % MODULUS + 1;
            }
        }
        #undef IDAT
        if (idv < 0) idv = 0;
        if (idv > 65535) idv = 65535;
        sh_id[tid] = (int)idv;
    }
    __syncthreads();

    __half* dst = g_mem_h + (size_t)tok * HIDDEN;
#pragma unroll
    for (int h = 0; h < 8; h++) {
        size_t src = ((size_t)h * 65536 + (size_t)sh_id[h]) * 256 + 2 * tid;
        float2 v = *(const float2*)(tables + src);
        *(__half2*)(dst + h * 256 + 2 * tid) = __floats2half2_rn(v.x, v.y);
    }
}

// ============================================================================
// Kernel 2: fused dual GEMM  C = memory @ W^T, fp16 mma.sync m16n8k16.
// BM=128 BN=128 BK=32 (halves), 3-stage cp.async, 48KB static smem.
// Swizzle: 16B chunk c of row r stored at  r*64 + ((c ^ ((r>>1)&3))<<4)
//   -> conflict-free ldmatrix (even/odd rows each cover 4 distinct chunk
//      slots mod 128B) and conflict-free stores.
// grid = (32, 128): x = n-block (16 Wk + 16 Wv, fast -> A tile L2 reuse).
// ============================================================================
#define BM 128
#define BN 128
#define BK 32
#define NSTAGE 3
#define STG_A (BM * BK * 2)       // 8192 B
#define STG_BYTES (2 * STG_A)     // 16384 B (A then B)

__device__ __forceinline__ void cp16g(uint32_t smem_dst, const void* gsrc) {
    asm volatile("cp.async.cg.shared.global [%0], [%1], 16;"
                 :: "r"(smem_dst), "l"(gsrc));
}

__global__ __launch_bounds__(256) void k_gemm()
{
    __shared__ __align__(128) uint8_t smbuf[NSTAGE * STG_BYTES];
    const uint32_t sbase = (uint32_t)__cvta_generic_to_shared(smbuf);

    const int bn  = blockIdx.x;           // 0..31 (fast)
    const int bm  = blockIdx.y;           // 0..127
    const int tid = threadIdx.x;

    const __half* A = g_mem_h + (size_t)bm * BM * HIDDEN;
    const int sel   = bn >> 4;            // 0 = Wk, 1 = Wv
    const int nloc  = (bn & 15) * BN;
    const __half* Bg = g_w_h + (size_t)sel * HIDDEN * HIDDEN + (size_t)nloc * HIDDEN;
    float* Cg = (sel ? g_val : g_key) + (size_t)bm * BM * HIDDEN + nloc;

    const int warp = tid >> 5;
    const int lane = tid & 31;
    const int wm = (warp & 1) * 64;       // warp M offset
    const int wn = (warp >> 1) * 32;      // warp N offset
    const int g  = lane >> 2;
    const int c  = lane & 3;

    // ldmatrix per-lane row/chunk components
    const int lrow = (lane & 7) + ((lane >> 3) & 1) * 8;  // row within 16
    const int lch  = lane >> 4;                            // chunk +0/+1

    // copy slots: 2 per tile per thread (512 chunk-slots / 256 threads)
    int crow[2], coff[2], cch[2];
#pragma unroll
    for (int j = 0; j < 2; j++) {
        int slot = tid + j * 256;
        int r = slot >> 2, ch = slot & 3;
        crow[j] = r;
        cch[j]  = ch;
        coff[j] = r * 64 + ((ch ^ ((r >> 1) & 3)) << 4);
    }

    float acc[4][4][4];
#pragma unroll
    for (int mt = 0; mt < 4; mt++)
#pragma unroll
        for (int nt = 0; nt < 4; nt++)
#pragma unroll
            for (int i = 0; i < 4; i++) acc[mt][nt][i] = 0.f;

    const int NST = HIDDEN / BK;          // 64 k-tiles

    // ---- prologue: stages 0, 1 ----
#pragma unroll
    for (int st = 0; st < 2; st++) {
        const uint32_t sA = sbase + st * STG_BYTES;
        const uint32_t sB = sA + STG_A;
        const int kk = st * BK;
#pragma unroll
        for (int j = 0; j < 2; j++) {
            cp16g(sA + coff[j], A  + (size_t)crow[j] * HIDDEN + kk + cch[j] * 8);
            cp16g(sB + coff[j], Bg + (size_t)crow[j] * HIDDEN + kk + cch[j] * 8);
        }
        asm volatile("cp.async.commit_group;" ::: "memory");
    }

    for (int i = 0; i < NST; i++) {
        asm volatile("cp.async.wait_group 1;" ::: "memory");
        __syncthreads();

        const int nxt = i + 2;
        if (nxt < NST) {
            const uint32_t sA = sbase + (nxt % NSTAGE) * STG_BYTES;
            const uint32_t sB = sA + STG_A;
            const int kk = nxt * BK;
#pragma unroll
            for (int j = 0; j < 2; j++) {
                cp16g(sA + coff[j], A  + (size_t)crow[j] * HIDDEN + kk + cch[j] * 8);
                cp16g(sB + coff[j], Bg + (size_t)crow[j] * HIDDEN + kk + cch[j] * 8);
            }
        }
        asm volatile("cp.async.commit_group;" ::: "memory");

        const uint32_t sA = sbase + (i % NSTAGE) * STG_BYTES;
        const uint32_t sB = sA + STG_A;

#pragma unroll
        for (int ks = 0; ks < 2; ks++) {
            const int chb = ks * 2 + lch;
            uint32_t a[4][4], bf[4][2];

            // A fragments: 4 x ldmatrix.x4 (m16 x k16 each)
#pragma unroll
            for (int mt = 0; mt < 4; mt++) {
                int r = wm + mt * 16 + lrow;
                uint32_t addr = sA + r * 64 + ((chb ^ ((r >> 1) & 3)) << 4);
                asm volatile(
                    "ldmatrix.sync.aligned.m8n8.x4.shared.b16 {%0,%1,%2,%3}, [%4];"
                    : "=r"(a[mt][0]), "=r"(a[mt][1]), "=r"(a[mt][2]), "=r"(a[mt][3])
                    : "r"(addr));
            }
            // B fragments: 2 x ldmatrix.x4 (each covers 2 n-tiles x k16)
#pragma unroll
            for (int p = 0; p < 2; p++) {
                int r = wn + p * 16 + lrow;
                uint32_t addr = sB + r * 64 + ((chb ^ ((r >> 1) & 3)) << 4);
                uint32_t t0, t1, t2, t3;
                asm volatile(
                    "ldmatrix.sync.aligned.m8n8.x4.shared.b16 {%0,%1,%2,%3}, [%4];"
                    : "=r"(t0), "=r"(t1), "=r"(t2), "=r"(t3) : "r"(addr));
                bf[2 * p][0]     = t0; bf[2 * p][1]     = t2;
                bf[2 * p + 1][0] = t1; bf[2 * p + 1][1] = t3;
            }

#pragma unroll
            for (int mt = 0; mt < 4; mt++)
#pragma unroll
                for (int nt = 0; nt < 4; nt++) {
                    asm volatile(
                        "mma.sync.aligned.m16n8k16.row.col.f32.f16.f16.f32 "
                        "{%0,%1,%2,%3},{%4,%5,%6,%7},{%8,%9},{%0,%1,%2,%3};"
                        : "+f"(acc[mt][nt][0]), "+f"(acc[mt][nt][1]),
                          "+f"(acc[mt][nt][2]), "+f"(acc[mt][nt][3])
                        : "r"(a[mt][0]), "r"(a[mt][1]), "r"(a[mt][2]), "r"(a[mt][3]),
                          "r"(bf[nt][0]), "r"(bf[nt][1]));
                }
        }
    }

    // ---- epilogue ----
#pragma unroll
    for (int mt = 0; mt < 4; mt++) {
#pragma unroll
        for (int nt = 0; nt < 4; nt++) {
            int rr = wm + mt * 16 + g;
            int cc = wn + nt * 8 + c * 2;
            *(float2*)(Cg + (size_t)rr * HIDDEN + cc) =
                make_float2(acc[mt][nt][0], acc[mt][nt][1]);
            *(float2*)(Cg + (size_t)(rr + 8) * HIDDEN + cc) =
                make_float2(acc[mt][nt][2], acc[mt][nt][3]);
        }
    }
}

// ============================================================================
// Kernel 3: per-token rmsnorm(key), rmsnorm(value), gate, gated value.
// Writes gated IN PLACE into g_key.
// ============================================================================
__global__ void k_gate(const float* __restrict__ hidden,
                       const float* __restrict__ kw,
                       const float* __restrict__ vw)
{
    const int tok = blockIdx.x;
    const int tid = threadIdx.x;
    const float* key = g_key + (size_t)tok * HIDDEN;
    const float* val = g_val + (size_t)tok * HIDDEN;
    const float* hh  = hidden + (size_t)tok * HIDDEN;

    float vv[8], wvv[8];
    float s1 = 0.f, s2 = 0.f, s3 = 0.f;
#pragma unroll
    for (int i = 0; i < 8; i++) {
        int d = tid + i * 256;
        float k = key[d];
        float v = val[d];
        float h = hh[d];
        float wk = kw[d];
        wvv[i] = vw[d];
        vv[i]  = v;
        s1 += k * k;
        s2 += v * v;
        s3 += h * wk * k;
    }
#pragma unroll
    for (int o = 16; o; o >>= 1) {
        s1 += __shfl_xor_sync(0xffffffffu, s1, o);
        s2 += __shfl_xor_sync(0xffffffffu, s2, o);
        s3 += __shfl_xor_sync(0xffffffffu, s3, o);
    }
    __shared__ float red[3][8];
    if ((tid & 31) == 0) {
        red[0][tid >> 5] = s1;
        red[1][tid >> 5] = s2;
        red[2][tid >> 5] = s3;
    }
    __syncthreads();
    float S1 = 0.f, S2 = 0.f, S3 = 0.f;
#pragma unroll
    for (int w = 0; w < 8; w++) { S1 += red[0][w]; S2 += red[1][w]; S3 += red[2][w]; }

    const float rk = rsqrtf(S1 * (1.0f / HIDDEN) + 1e-6f);
    const float rv = rsqrtf(S2 * (1.0f / HIDDEN) + 1e-6f);
    const float logit = S3 * rk * (1.0f / 45.254833995939045f) + GATE_BIAS;
    const float gate  = 1.0f / (1.0f + expf(-logit));

    float* out = g_key + (size_t)tok * HIDDEN;
#pragma unroll
    for (int i = 0; i < 8; i++) {
        int d = tid + i * 256;
        out[d] = gate * wvv[i] * vv[i] * rv;
    }
}

// ============================================================================
// Kernel 4: causal depthwise conv (K=3) + residual, gated lives in g_key.
// ============================================================================
__global__ void k_conv(const float* __restrict__ conv_w,
                       float* __restrict__ out)
{
    const int tok = blockIdx.y;
    const int d   = blockIdx.x * 256 + threadIdx.x;
    const int s   = tok & (SEQ - 1);
    const size_t base = (size_t)tok * HIDDEN + d;

    float g2 = g_key[base];
    float g1 = (s >= 1) ? g_key[base - HIDDEN]     : 0.f;
    float g0 = (s >= 2) ? g_key[base - 2 * HIDDEN] : 0.f;
    float w0 = conv_w[d * 3 + 0];
    float w1 = conv_w[d * 3 + 1];
    float w2 = conv_w[d * 3 + 2];
    out[base] = g2 + w0 * g0 + w1 * g1 + w2 * g2;
}

// ============================================================================
extern "C" void kernel_launch(void* const* d_in, const int* in_sizes, int n_in,
                              void* d_out, int out_size)
{
    const float* hidden = nullptr;
    const void*  ids    = nullptr;
    const float* tables = nullptr;
    const float* Wk = nullptr, *Wv = nullptr;
    const float* knw = nullptr, *vnw = nullptr;
    const float* convw = nullptr;
    const int*   hm2 = nullptr, *ho2 = nullptr, *hm3 = nullptr, *ho3 = nullptr;

    for (int i = 0; i < n_in; i++) {
        const int sz = in_sizes[i];
        void* p = d_in[i];
        switch (sz) {
            case 33554432:  hidden = (const float*)p; break;
            case 16384:     ids    = (const void*)p; break;
            case 134217728: tables = (const float*)p; break;
            case 4194304:   if (!Wk) Wk = (const float*)p; else Wv = (const float*)p; break;
            case 2048:      if (!knw) knw = (const float*)p; else vnw = (const float*)p; break;
            case 6144:      convw = (const float*)p; break;
            case 8:         hm2 = (const int*)p; break;
            case 12:        hm3 = (const int*)p; break;
            case 4:         if (!ho2) ho2 = (const int*)p; else ho3 = (const int*)p; break;
            default: break;
        }
    }
    float* out = (float*)d_out;

    k_norm<<<1, 1>>>(hm2, ho2, hm3, ho3, (const int*)ids);
    k_roundW<<<HIDDEN * HIDDEN / 512, 256>>>(Wk, Wv);
    k_hash_gather<<<NTOK, 128>>>(ids, tables);
    k_gemm<<<dim3(32, NTOK / BM), 256>>>();
    k_gate<<<NTOK, 256>>>(hidden, knw, vnw);
    k_conv<<<dim3(HIDDEN / 256, NTOK), 256>>>(convw, out);
}

// round 7
// speedup vs baseline: 2.3599x; 1.1636x over previous
#include <cuda_runtime.h>
#include <cuda_fp16.h>
#include <cstdint>

#define HIDDEN   2048
#define SEQ      4096
#define NTOK     16384          // B*S = 4*4096
#define MODULUS  65535LL
#define GATE_BIAS (-4.0f)

// -------- static scratch (no dynamic allocation allowed) --------
__device__ __half g_mem_h[(size_t)NTOK * HIDDEN];        // gathered rows (fp16)
__device__ __half g_w_h  [(size_t)2 * HIDDEN * HIDDEN];  // fp16 Wk|Wv
__device__ float  g_key  [(size_t)NTOK * HIDDEN];        // Wk out, then gated
__device__ float  g_val  [(size_t)NTOK * HIDDEN];        // Wv out

// normalized hash params (always int64 semantics of the reference)
__device__ long long n_hm2[8];
__device__ long long n_ho2[4];
__device__ long long n_hm3[12];
__device__ long long n_ho3[4];
__device__ int       g_ids_is32;

// ============================================================================
// Kernel 0: detect storage width of integer inputs, normalize params to i64.
// ============================================================================
__global__ void k_norm(const int* __restrict__ hm2, const int* __restrict__ ho2,
                       const int* __restrict__ hm3, const int* __restrict__ ho3,
                       const int* __restrict__ ids)
{
    const bool p64 = (hm2[1] == 0) && (hm2[3] == 0) && (hm2[5] == 0) && (hm2[7] == 0);
    if (p64) {
        const long long* h2 = (const long long*)hm2;
        const long long* o2 = (const long long*)ho2;
        const long long* h3 = (const long long*)hm3;
        const long long* o3 = (const long long*)ho3;
        for (int i = 0; i < 8;  i++) n_hm2[i] = h2[i];
        for (int i = 0; i < 4;  i++) n_ho2[i] = o2[i];
        for (int i = 0; i < 12; i++) n_hm3[i] = h3[i];
        for (int i = 0; i < 4;  i++) n_ho3[i] = o3[i];
    } else {
        for (int i = 0; i < 8;  i++) n_hm2[i] = (long long)(unsigned int)hm2[i];
        for (int i = 0; i < 4;  i++) n_ho2[i] = (long long)(unsigned int)ho2[i];
        for (int i = 0; i < 12; i++) n_hm3[i] = (long long)(unsigned int)hm3[i];
        for (int i = 0; i < 4;  i++) n_ho3[i] = (long long)(unsigned int)ho3[i];
    }
    bool i64 = true;
    for (int i = 1; i < 64; i += 2) {
        if (ids[i] != 0) { i64 = false; break; }
    }
    g_ids_is32 = i64 ? 0 : 1;
}

// ============================================================================
// Kernel 0b: fp16-round Wk|Wv into g_w_h (half2 stores).
// ============================================================================
__global__ void k_roundW(const float* __restrict__ Wk, const float* __restrict__ Wv)
{
    size_t i = (size_t)blockIdx.x * 256 + threadIdx.x;   // pair index
    float2 a = *(const float2*)(Wk + 2 * i);
    float2 b = *(const float2*)(Wv + 2 * i);
    *(__half2*)(g_w_h + 2 * i) = __floats2half2_rn(a.x, a.y);
    *(__half2*)(g_w_h + (size_t)HIDDEN * HIDDEN + 2 * i) = __floats2half2_rn(b.x, b.y);
}

// ============================================================================
// Kernel 1: n-gram hashing + table gather (fp16 output, half2 stores).
// ============================================================================
__global__ void k_hash_gather(const void* __restrict__ ids_raw,
                              const float* __restrict__ tables)
{
    const int tok = blockIdx.x;
    const int tid = threadIdx.x;          // 0..127
    const int b = tok >> 12;
    const int s = tok & (SEQ - 1);

    __shared__ int sh_id[8];
    if (tid < 8) {
        const int head = tid & 3;
        const int ng   = tid >> 2;
        const int is32 = g_ids_is32;
        const long long* row64 = (const long long*)ids_raw + (size_t)b * SEQ;
        const int*       row32 = (const int*)      ids_raw + (size_t)b * SEQ;
        #define IDAT(x) (is32 ? (long long)row32[(x)] : row64[(x)])
        long long idv = 0;
        if (ng == 0) {
            if (s >= 1) {
                long long mix = (IDAT(s - 1) * n_hm2[head * 2 + 0])
                              ^ (IDAT(s)     * n_hm2[head * 2 + 1]);
                idv = (mix + n_ho2[head]) % MODULUS + 1;
            }
        } else {
            if (s >= 2) {
                long long mix = (IDAT(s - 2) * n_hm3[head * 3 + 0])
                              ^ (IDAT(s - 1) * n_hm3[head * 3 + 1])
                              ^ (IDAT(s)     * n_hm3[head * 3 + 2]);
                idv = (mix + n_ho3[head]) % MODULUS + 1;
            }
        }
        #undef IDAT
        if (idv < 0) idv = 0;
        if (idv > 65535) idv = 65535;
        sh_id[tid] = (int)idv;
    }
    __syncthreads();

    __half* dst = g_mem_h + (size_t)tok * HIDDEN;
#pragma unroll
    for (int h = 0; h < 8; h++) {
        size_t src = ((size_t)h * 65536 + (size_t)sh_id[h]) * 256 + 2 * tid;
        float2 v = *(const float2*)(tables + src);
        *(__half2*)(dst + h * 256 + 2 * tid) = __floats2half2_rn(v.x, v.y);
    }
}

// ============================================================================
// Kernel 2: fused dual GEMM  C = memory @ W^T, fp16 mma.sync m16n8k16.
// BM=128 BN=128 BK=32, 3-stage cp.async, all addresses hoisted, k-loop
// unrolled by 3 so stage bases are compile-time.
// ============================================================================
#define BM 128
#define BN 128
#define BK 32
#define STG_A (BM * BK * 2)       // 8192 B
#define STG_BYTES (2 * STG_A)     // 16384 B (A then B)
#define NST 64                    // HIDDEN / BK

__device__ __forceinline__ void cp16g(uint32_t smem_dst, const void* gsrc) {
    asm volatile("cp.async.cg.shared.global [%0], [%1], 16;"
                 :: "r"(smem_dst), "l"(gsrc));
}

__global__ __launch_bounds__(256) void k_gemm()
{
    __shared__ __align__(128) uint8_t smbuf[3 * STG_BYTES];
    const uint32_t sbase = (uint32_t)__cvta_generic_to_shared(smbuf);

    const int bn  = blockIdx.x;           // 0..31 (fast)
    const int bm  = blockIdx.y;           // 0..127
    const int tid = threadIdx.x;

    const __half* A = g_mem_h + (size_t)bm * BM * HIDDEN;
    const int sel   = bn >> 4;            // 0 = Wk, 1 = Wv
    const int nloc  = (bn & 15) * BN;
    const __half* Bg = g_w_h + (size_t)sel * HIDDEN * HIDDEN + (size_t)nloc * HIDDEN;
    float* Cg = (sel ? g_val : g_key) + (size_t)bm * BM * HIDDEN + nloc;

    const int warp = tid >> 5;
    const int lane = tid & 31;
    const int wm = (warp & 1) * 64;
    const int wn = (warp >> 1) * 32;
    const int g  = lane >> 2;
    const int c  = lane & 3;
    const int lrow = (lane & 7) + ((lane >> 3) & 1) * 8;
    const int lch  = lane >> 4;

    // ---- hoisted copy slots (2 A-chunks + 2 B-chunks per thread) ----
    uint32_t coff[2];
    const __half* pa[2];
    const __half* pb[2];
#pragma unroll
    for (int j = 0; j < 2; j++) {
        int slot = tid + j * 256;
        int r = slot >> 2, ch = slot & 3;
        coff[j] = r * 64 + ((ch ^ ((r >> 1) & 3)) << 4);
        pa[j] = A  + (size_t)r * HIDDEN + ch * 8;
        pb[j] = Bg + (size_t)r * HIDDEN + ch * 8;
    }

    // ---- hoisted fragment offsets ----
    uint32_t offA[4][2], offB[2][2];
#pragma unroll
    for (int mt = 0; mt < 4; mt++) {
        int r = wm + mt * 16 + lrow;
#pragma unroll
        for (int ks = 0; ks < 2; ks++)
            offA[mt][ks] = r * 64 + (((ks * 2 + lch) ^ ((r >> 1) & 3)) << 4);
    }
#pragma unroll
    for (int p = 0; p < 2; p++) {
        int r = wn + p * 16 + lrow;
#pragma unroll
        for (int ks = 0; ks < 2; ks++)
            offB[p][ks] = r * 64 + (((ks * 2 + lch) ^ ((r >> 1) & 3)) << 4);
    }

    float acc[4][4][4];
#pragma unroll
    for (int mt = 0; mt < 4; mt++)
#pragma unroll
        for (int nt = 0; nt < 4; nt++)
#pragma unroll
            for (int i = 0; i < 4; i++) acc[mt][nt][i] = 0.f;

    // ---- prologue: stages 0, 1 ----
#pragma unroll
    for (int st = 0; st < 2; st++) {
        const uint32_t sA = sbase + st * STG_BYTES;
        cp16g(sA + coff[0],         pa[0] + st * BK);
        cp16g(sA + coff[1],         pa[1] + st * BK);
        cp16g(sA + STG_A + coff[0], pb[0] + st * BK);
        cp16g(sA + STG_A + coff[1], pb[1] + st * BK);
        asm volatile("cp.async.commit_group;" ::: "memory");
    }

#define GEMM_BODY(T, S)                                                        \
    do {                                                                       \
        asm volatile("cp.async.wait_group 1;" ::: "memory");                   \
        __syncthreads();                                                       \
        {                                                                      \
            const int nxt = (T) + 2;                                           \
            if (nxt < NST) {                                                   \
                const uint32_t dA = sbase + (((S) + 2) % 3) * STG_BYTES;       \
                cp16g(dA + coff[0],         pa[0] + nxt * BK);                 \
                cp16g(dA + coff[1],         pa[1] + nxt * BK);                 \
                cp16g(dA + STG_A + coff[0], pb[0] + nxt * BK);                 \
                cp16g(dA + STG_A + coff[1], pb[1] + nxt * BK);                 \
            }                                                                  \
            asm volatile("cp.async.commit_group;" ::: "memory");               \
        }                                                                      \
        {                                                                      \
            const uint32_t sA = sbase + (S) * STG_BYTES;                       \
            const uint32_t sB = sA + STG_A;                                    \
            uint32_t af[2][4][4], bf[2][4][2];                                 \
            _Pragma("unroll")                                                  \
            for (int ks = 0; ks < 2; ks++) {                                   \
                _Pragma("unroll")                                              \
                for (int mt = 0; mt < 4; mt++)                                 \
                    asm volatile(                                              \
                        "ldmatrix.sync.aligned.m8n8.x4.shared.b16 "            \
                        "{%0,%1,%2,%3}, [%4];"                                 \
                        : "=r"(af[ks][mt][0]), "=r"(af[ks][mt][1]),            \
                          "=r"(af[ks][mt][2]), "=r"(af[ks][mt][3])             \
                        : "r"(sA + offA[mt][ks]));                             \
                _Pragma("unroll")                                              \
                for (int p = 0; p < 2; p++) {                                  \
                    uint32_t t0, t1, t2, t3;                                   \
                    asm volatile(                                              \
                        "ldmatrix.sync.aligned.m8n8.x4.shared.b16 "            \
                        "{%0,%1,%2,%3}, [%4];"                                 \
                        : "=r"(t0), "=r"(t1), "=r"(t2), "=r"(t3)               \
                        : "r"(sB + offB[p][ks]));                              \
                    bf[ks][2 * p][0]     = t0; bf[ks][2 * p][1]     = t2;      \
                    bf[ks][2 * p + 1][0] = t1; bf[ks][2 * p + 1][1] = t3;      \
                }                                                              \
            }                                                                  \
            _Pragma("unroll")                                                  \
            for (int ks = 0; ks < 2; ks++)                                     \
                _Pragma("unroll")                                              \
                for (int mt = 0; mt < 4; mt++)                                 \
                    _Pragma("unroll")                                          \
                    for (int nt = 0; nt < 4; nt++)                             \
                        asm volatile(                                          \
                            "mma.sync.aligned.m16n8k16.row.col.f32.f16.f16.f32 " \
                            "{%0,%1,%2,%3},{%4,%5,%6,%7},{%8,%9},{%0,%1,%2,%3};" \
                            : "+f"(acc[mt][nt][0]), "+f"(acc[mt][nt][1]),      \
                              "+f"(acc[mt][nt][2]), "+f"(acc[mt][nt][3])       \
                            : "r"(af[ks][mt][0]), "r"(af[ks][mt][1]),          \
                              "r"(af[ks][mt][2]), "r"(af[ks][mt][3]),          \
                              "r"(bf[ks][nt][0]), "r"(bf[ks][nt][1]));         \
        }                                                                      \
    } while (0)

    for (int t = 0; t < NST - 1; t += 3) {
        GEMM_BODY(t,     0);
        GEMM_BODY(t + 1, 1);
        GEMM_BODY(t + 2, 2);
    }
    GEMM_BODY(NST - 1, 0);   // tile 63, stage 63%3 = 0

#undef GEMM_BODY

    // ---- epilogue ----
#pragma unroll
    for (int mt = 0; mt < 4; mt++) {
#pragma unroll
        for (int nt = 0; nt < 4; nt++) {
            int rr = wm + mt * 16 + g;
            int cc = wn + nt * 8 + c * 2;
            *(float2*)(Cg + (size_t)rr * HIDDEN + cc) =
                make_float2(acc[mt][nt][0], acc[mt][nt][1]);
            *(float2*)(Cg + (size_t)(rr + 8) * HIDDEN + cc) =
                make_float2(acc[mt][nt][2], acc[mt][nt][3]);
        }
    }
}

// ============================================================================
// Kernel 3: per-token rmsnorm(key), rmsnorm(value), gate, gated value.
// Writes gated IN PLACE into g_key.
// ============================================================================
__global__ void k_gate(const float* __restrict__ hidden,
                       const float* __restrict__ kw,
                       const float* __restrict__ vw)
{
    const int tok = blockIdx.x;
    const int tid = threadIdx.x;
    const float* key = g_key + (size_t)tok * HIDDEN;
    const float* val = g_val + (size_t)tok * HIDDEN;
    const float* hh  = hidden + (size_t)tok * HIDDEN;

    float vv[8], wvv[8];
    float s1 = 0.f, s2 = 0.f, s3 = 0.f;
#pragma unroll
    for (int i = 0; i < 8; i++) {
        int d = tid + i * 256;
        float k = key[d];
        float v = val[d];
        float h = hh[d];
        float wk = kw[d];
        wvv[i] = vw[d];
        vv[i]  = v;
        s1 += k * k;
        s2 += v * v;
        s3 += h * wk * k;
    }
#pragma unroll
    for (int o = 16; o; o >>= 1) {
        s1 += __shfl_xor_sync(0xffffffffu, s1, o);
        s2 += __shfl_xor_sync(0xffffffffu, s2, o);
        s3 += __shfl_xor_sync(0xffffffffu, s3, o);
    }
    __shared__ float red[3][8];
    if ((tid & 31) == 0) {
        red[0][tid >> 5] = s1;
        red[1][tid >> 5] = s2;
        red[2][tid >> 5] = s3;
    }
    __syncthreads();
    float S1 = 0.f, S2 = 0.f, S3 = 0.f;
#pragma unroll
    for (int w = 0; w < 8; w++) { S1 += red[0][w]; S2 += red[1][w]; S3 += red[2][w]; }

    const float rk = rsqrtf(S1 * (1.0f / HIDDEN) + 1e-6f);
    const float rv = rsqrtf(S2 * (1.0f / HIDDEN) + 1e-6f);
    const float logit = S3 * rk * (1.0f / 45.254833995939045f) + GATE_BIAS;
    const float gate  = 1.0f / (1.0f + expf(-logit));

    float* out = g_key + (size_t)tok * HIDDEN;
#pragma unroll
    for (int i = 0; i < 8; i++) {
        int d = tid + i * 256;
        out[d] = gate * wvv[i] * vv[i] * rv;
    }
}

// ============================================================================
// Kernel 4: causal depthwise conv (K=3) + residual, gated lives in g_key.
// ============================================================================
__global__ void k_conv(const float* __restrict__ conv_w,
                       float* __restrict__ out)
{
    const int tok = blockIdx.y;
    const int d   = blockIdx.x * 256 + threadIdx.x;
    const int s   = tok & (SEQ - 1);
    const size_t base = (size_t)tok * HIDDEN + d;

    float g2 = g_key[base];
    float g1 = (s >= 1) ? g_key[base - HIDDEN]     : 0.f;
    float g0 = (s >= 2) ? g_key[base - 2 * HIDDEN] : 0.f;
    float w0 = conv_w[d * 3 + 0];
    float w1 = conv_w[d * 3 + 1];
    float w2 = conv_w[d * 3 + 2];
    out[base] = g2 + w0 * g0 + w1 * g1 + w2 * g2;
}

// ============================================================================
extern "C" void kernel_launch(void* const* d_in, const int* in_sizes, int n_in,
                              void* d_out, int out_size)
{
    const float* hidden = nullptr;
    const void*  ids    = nullptr;
    const float* tables = nullptr;
    const float* Wk = nullptr, *Wv = nullptr;
    const float* knw = nullptr, *vnw = nullptr;
    const float* convw = nullptr;
    const int*   hm2 = nullptr, *ho2 = nullptr, *hm3 = nullptr, *ho3 = nullptr;

    for (int i = 0; i < n_in; i++) {
        const int sz = in_sizes[i];
        void* p = d_in[i];
        switch (sz) {
            case 33554432:  hidden = (const float*)p; break;
            case 16384:     ids    = (const void*)p; break;
            case 134217728: tables = (const float*)p; break;
            case 4194304:   if (!Wk) Wk = (const float*)p; else Wv = (const float*)p; break;
            case 2048:      if (!knw) knw = (const float*)p; else vnw = (const float*)p; break;
            case 6144:      convw = (const float*)p; break;
            case 8:         hm2 = (const int*)p; break;
            case 12:        hm3 = (const int*)p; break;
            case 4:         if (!ho2) ho2 = (const int*)p; else ho3 = (const int*)p; break;
            default: break;
        }
    }
    float* out = (float*)d_out;

    k_norm<<<1, 1>>>(hm2, ho2, hm3, ho3, (const int*)ids);
    k_roundW<<<HIDDEN * HIDDEN / 512, 256>>>(Wk, Wv);
    k_hash_gather<<<NTOK, 128>>>(ids, tables);
    k_gemm<<<dim3(32, NTOK / BM), 256>>>();
    k_gate<<<NTOK, 256>>>(hidden, knw, vnw);
    k_conv<<<dim3(HIDDEN / 256, NTOK), 256>>>(convw, out);
}